// round 1
// baseline (speedup 1.0000x reference)
#include <cuda_runtime.h>

#define BRANCHES 4
#define NB 16
#define CPB 64      // channels per branch
#define HGT 80
#define WID 80
#define NPIX 6400
#define NHEADS 8

// ---------------- scratch (device globals; no runtime allocation) ----------
__device__ float g_y  [(size_t)BRANCHES*NB*CPB*NPIX];            // dwconv out [br][b][c][n]
__device__ float g_q  [(size_t)BRANCHES*NB*CPB*NPIX];            // q [br][b][h*8+d][n]
__device__ float g_k  [(size_t)BRANCHES*NB*NHEADS*NPIX*8];       // k (softmaxed) [br][b][h][n][d]
__device__ float g_v  [(size_t)BRANCHES*NB*NHEADS*NPIX*8];       // v [br][b][h][n][d]
__device__ float g_ctx[(size_t)BRANCHES*NB*NHEADS*64];           // ctx [br][b][h][d*8+e]
__device__ float g_att[(size_t)BRANCHES*NB*CPB*NPIX];            // branch attention out [br][b][o][n']

// ---------------- K1: depthwise conv + bias + residual + relu --------------
// grid (5 row-tiles, 64 channels, 16 batch), block 320 = 20x16
template<int KS>
__global__ void dwconv_kernel(const float* __restrict__ x,
                              const float* __restrict__ w,
                              const float* __restrict__ bias,
                              int br)
{
    __shared__ float tile[24*88];
    __shared__ float wsm[KS*KS];
    const int b    = blockIdx.z;
    const int c    = blockIdx.y;
    const int row0 = blockIdx.x * 16;
    const int tid  = threadIdx.x;

    if (tid < KS*KS) wsm[tid] = w[c*KS*KS + tid];
    const float bv = bias[c];
    const float* xp = x + ((size_t)b*256 + (size_t)br*64 + c) * NPIX;

    for (int idx = tid; idx < 24*88; idx += 320) {
        int r  = idx / 88, cl = idx % 88;
        int gh = row0 - 4 + r, gw = cl - 4;
        float v = 0.f;
        if (gh >= 0 && gh < HGT && gw >= 0 && gw < WID) v = xp[gh*WID + gw];
        tile[idx] = v;
    }
    __syncthreads();

    const int tx = tid % 20, ty = tid / 20;
    const int col0 = tx * 4;
    constexpr int PAD = KS / 2;
    float a0 = 0.f, a1 = 0.f, a2 = 0.f, a3 = 0.f;
    #pragma unroll
    for (int kh = 0; kh < KS; kh++) {
        int base = (ty + 4 - PAD + kh)*88 + col0 + 4 - PAD;
        #pragma unroll
        for (int kw = 0; kw < KS; kw++) {
            float wv = wsm[kh*KS + kw];
            a0 += tile[base + kw    ] * wv;
            a1 += tile[base + kw + 1] * wv;
            a2 += tile[base + kw + 2] * wv;
            a3 += tile[base + kw + 3] * wv;
        }
    }
    int cb = (ty + 4)*88 + col0 + 4;
    float* yp = g_y + (((size_t)br*NB + b)*CPB + c)*NPIX + (row0 + ty)*WID + col0;
    yp[0] = fmaxf(a0 + bv + tile[cb + 0], 0.f);
    yp[1] = fmaxf(a1 + bv + tile[cb + 1], 0.f);
    yp[2] = fmaxf(a2 + bv + tile[cb + 2], 0.f);
    yp[3] = fmaxf(a3 + bv + tile[cb + 3], 0.f);
}

// ---------------- K2: qkv GEMM + k-softmax + scatter ----------------------
// grid (100 token tiles, 64 br*b), block 256, dyn smem 65536B
__global__ void qkv_kernel(const float* __restrict__ wqkv)
{
    extern __shared__ float sm[];
    float* wq = sm;               // 192*64 = 12288 floats
    float* ys = sm + 12288;       // 64*64  =  4096 floats
    const int tid = threadIdx.x;
    const int brb = blockIdx.y;
    const int n0  = blockIdx.x * 64;

    const float* yp = g_y + (size_t)brb * CPB * NPIX;
    for (int idx = tid; idx < 192*64; idx += 256) wq[idx] = wqkv[idx];
    for (int idx = tid; idx < 64*64;  idx += 256) {
        int c = idx >> 6, t = idx & 63;
        ys[idx] = yp[(size_t)c*NPIX + n0 + t];
    }
    __syncthreads();

    const int tok = (tid & 15) * 4;
    const int j0  = (tid >> 4) * 12;
    float acc[12][4];
    #pragma unroll
    for (int jj = 0; jj < 12; jj++) { acc[jj][0]=acc[jj][1]=acc[jj][2]=acc[jj][3]=0.f; }

    for (int c = 0; c < 64; c++) {
        float4 ya = *(const float4*)&ys[c*64 + tok];
        #pragma unroll
        for (int jj = 0; jj < 12; jj++) {
            float wv = wq[(j0 + jj)*64 + c];
            acc[jj][0] += ya.x * wv;
            acc[jj][1] += ya.y * wv;
            acc[jj][2] += ya.z * wv;
            acc[jj][3] += ya.w * wv;
        }
    }
    __syncthreads();   // all reads of wq/ys done before overlay

    float* qkvs = sm;  // 64*193 = 12352 floats, padded stride vs bank conflicts
    #pragma unroll
    for (int jj = 0; jj < 12; jj++)
        #pragma unroll
        for (int i = 0; i < 4; i++)
            qkvs[(tok + i)*193 + j0 + jj] = acc[jj][i];
    __syncthreads();

    // k softmax over head-dim (8) + write k, v
    for (int th = tid; th < 64*NHEADS; th += 256) {
        int t = th & 63, h = th >> 6;
        const float* kr = &qkvs[t*193 + 64 + h*8];
        float m = kr[0];
        #pragma unroll
        for (int d = 1; d < 8; d++) m = fmaxf(m, kr[d]);
        float e[8]; float s = 0.f;
        #pragma unroll
        for (int d = 0; d < 8; d++) { e[d] = __expf(kr[d] - m); s += e[d]; }
        float inv = 1.f / s;
        size_t kb = (((size_t)brb*NHEADS + h)*NPIX + n0 + t)*8;
        float4 k0 = make_float4(e[0]*inv, e[1]*inv, e[2]*inv, e[3]*inv);
        float4 k1 = make_float4(e[4]*inv, e[5]*inv, e[6]*inv, e[7]*inv);
        *(float4*)&g_k[kb]     = k0;
        *(float4*)&g_k[kb + 4] = k1;
        const float* vr = &qkvs[t*193 + 128 + h*8];
        float4 v0 = make_float4(vr[0], vr[1], vr[2], vr[3]);
        float4 v1 = make_float4(vr[4], vr[5], vr[6], vr[7]);
        *(float4*)&g_v[kb]     = v0;
        *(float4*)&g_v[kb + 4] = v1;
    }
    // q scatter (raw; token softmax later) to [br][b][hd][n]
    for (int idx = tid; idx < 64*64; idx += 256) {
        int hd = idx >> 6, t = idx & 63;
        g_q[((size_t)brb*64 + hd)*NPIX + n0 + t] = qkvs[t*193 + hd];
    }
}

// ---------------- K3: q softmax over tokens (n=6400) ----------------------
// grid 4096 rows, block 256
__global__ void qsoftmax_kernel()
{
    __shared__ float red[256];
    float* p = g_q + (size_t)blockIdx.x * NPIX;
    const int tid = threadIdx.x;

    float m = -1e30f;
    for (int i = tid; i < NPIX; i += 256) m = fmaxf(m, p[i]);
    red[tid] = m; __syncthreads();
    for (int s = 128; s; s >>= 1) { if (tid < s) red[tid] = fmaxf(red[tid], red[tid + s]); __syncthreads(); }
    m = red[0]; __syncthreads();

    float sum = 0.f;
    for (int i = tid; i < NPIX; i += 256) sum += __expf(p[i] - m);
    red[tid] = sum; __syncthreads();
    for (int s = 128; s; s >>= 1) { if (tid < s) red[tid] += red[tid + s]; __syncthreads(); }
    float inv = 1.f / red[0];

    for (int i = tid; i < NPIX; i += 256) p[i] = __expf(p[i] - m) * inv;
}

// ---------------- K4: ctx = sum_n k[n,d] * v[n,e] -------------------------
// grid 512 = br*b*h, block 256
__global__ void ctx_kernel()
{
    const int bh  = blockIdx.x;
    const int tid = threadIdx.x;
    const float* kp = g_k + (size_t)bh * NPIX * 8;
    const float* vp = g_v + (size_t)bh * NPIX * 8;

    float acc[8][8];
    #pragma unroll
    for (int d = 0; d < 8; d++)
        #pragma unroll
        for (int e = 0; e < 8; e++) acc[d][e] = 0.f;

    for (int n = tid; n < NPIX; n += 256) {
        float4 k0 = *(const float4*)&kp[(size_t)n*8];
        float4 k1 = *(const float4*)&kp[(size_t)n*8 + 4];
        float4 v0 = *(const float4*)&vp[(size_t)n*8];
        float4 v1 = *(const float4*)&vp[(size_t)n*8 + 4];
        float kk[8] = {k0.x,k0.y,k0.z,k0.w,k1.x,k1.y,k1.z,k1.w};
        float vv[8] = {v0.x,v0.y,v0.z,v0.w,v1.x,v1.y,v1.z,v1.w};
        #pragma unroll
        for (int d = 0; d < 8; d++)
            #pragma unroll
            for (int e = 0; e < 8; e++) acc[d][e] += kk[d] * vv[e];
    }
    #pragma unroll
    for (int off = 16; off; off >>= 1)
        #pragma unroll
        for (int d = 0; d < 8; d++)
            #pragma unroll
            for (int e = 0; e < 8; e++)
                acc[d][e] += __shfl_down_sync(0xffffffffu, acc[d][e], off);

    __shared__ float red[8][64];
    int lane = tid & 31, wp = tid >> 5;
    if (lane == 0) {
        #pragma unroll
        for (int i = 0; i < 64; i++) red[wp][i] = acc[i >> 3][i & 7];
    }
    __syncthreads();
    if (tid < 64) {
        float s = 0.f;
        #pragma unroll
        for (int w = 0; w < 8; w++) s += red[w][tid];
        g_ctx[(size_t)bh*64 + tid] = s;
    }
}

// ---------------- K5: out = q@ctx, scrambled reshape, proj, scale ---------
// grid (200 group-tiles, 64 br*b), block 256
__global__ void attn_out_kernel(const float* __restrict__ wproj,
                                const float* __restrict__ bproj,
                                const float* __restrict__ scale)
{
    __shared__ float wp   [64*68];   // [f][o] padded
    __shared__ float out_s[32*64];   // [g][f]
    __shared__ float p_s  [32*64];   // [g][o]
    __shared__ float ctx_s[64];
    const int tid = threadIdx.x;
    const int brb = blockIdx.y;
    const int br  = brb >> 4;
    const int g0  = blockIdx.x * 32;       // n' base; 800 % 32 == 0 -> one head per block
    const int h   = g0 / 800;

    for (int idx = tid; idx < 4096; idx += 256) {
        int o = idx >> 6, f = idx & 63;
        wp[f*68 + o] = wproj[idx];          // wproj[o][f]
    }
    if (tid < 64) ctx_s[tid] = g_ctx[((size_t)brb*NHEADS + h)*64 + tid];
    __syncthreads();

    // Phase A: out[g][i*8+e] = sum_d q[h,d,n0+i] * ctx[d,e]
    {
        int g = tid >> 3, i = tid & 7;
        int np = g0 + g;
        int n0 = (np % 800) * 8;
        const float* qp = g_q + ((size_t)brb*64 + h*8)*NPIX + n0 + i;
        float oo[8] = {0,0,0,0,0,0,0,0};
        #pragma unroll
        for (int d = 0; d < 8; d++) {
            float qv = qp[(size_t)d*NPIX];
            #pragma unroll
            for (int e = 0; e < 8; e++) oo[e] += qv * ctx_s[d*8 + e];
        }
        #pragma unroll
        for (int e = 0; e < 8; e++) out_s[g*64 + i*8 + e] = oo[e];
    }
    __syncthreads();

    // Phase B: p[g][o] = (sum_f out[g][f]*wproj[o][f] + bproj[o]) * scale[br]
    {
        int gp = tid >> 4;              // 0..15 -> groups 2gp, 2gp+1
        int o4 = (tid & 15) * 4;
        float p0[4] = {0,0,0,0}, p1[4] = {0,0,0,0};
        #pragma unroll
        for (int f = 0; f < 64; f++) {
            float a0 = out_s[(2*gp    )*64 + f];
            float a1 = out_s[(2*gp + 1)*64 + f];
            float4 w4 = *(const float4*)&wp[f*68 + o4];
            p0[0] += a0*w4.x; p0[1] += a0*w4.y; p0[2] += a0*w4.z; p0[3] += a0*w4.w;
            p1[0] += a1*w4.x; p1[1] += a1*w4.y; p1[2] += a1*w4.z; p1[3] += a1*w4.w;
        }
        float scl  = __ldg(&scale[br]);
        float4 bp4 = *(const float4*)&bproj[o4];
        float4 r0, r1;
        r0.x = (p0[0]+bp4.x)*scl; r0.y = (p0[1]+bp4.y)*scl;
        r0.z = (p0[2]+bp4.z)*scl; r0.w = (p0[3]+bp4.w)*scl;
        r1.x = (p1[0]+bp4.x)*scl; r1.y = (p1[1]+bp4.y)*scl;
        r1.z = (p1[2]+bp4.z)*scl; r1.w = (p1[3]+bp4.w)*scl;
        *(float4*)&p_s[(2*gp    )*64 + o4] = r0;
        *(float4*)&p_s[(2*gp + 1)*64 + o4] = r1;
    }
    __syncthreads();

    float* ap = g_att + (size_t)brb*64*NPIX;
    for (int idx = tid; idx < 64*8; idx += 256) {
        int o = idx >> 3, seg = idx & 7;
        float4 r;
        r.x = p_s[(seg*4 + 0)*64 + o];
        r.y = p_s[(seg*4 + 1)*64 + o];
        r.z = p_s[(seg*4 + 2)*64 + o];
        r.w = p_s[(seg*4 + 3)*64 + o];
        *(float4*)&ap[(size_t)o*NPIX + g0 + seg*4] = r;
    }
}

// ---------------- K6: final 256x256 GEMM over pixels -----------------------
// grid (100 n-tiles, 4 o-tiles, 16 b), block 256
__global__ void final_kernel(const float* __restrict__ wf,
                             const float* __restrict__ bf,
                             float* __restrict__ out)
{
    __shared__ float a_s[32*68];   // [k][o] padded
    __shared__ float b_s[32*64];   // [k][n]
    const int tid = threadIdx.x;
    const int n0  = blockIdx.x * 64;
    const int o0  = blockIdx.y * 64;
    const int b   = blockIdx.z;

    const int n4 = (tid & 15) * 4, o4 = (tid >> 4) * 4;
    float acc[4][4];
    #pragma unroll
    for (int i = 0; i < 4; i++)
        #pragma unroll
        for (int j = 0; j < 4; j++) acc[i][j] = 0.f;

    for (int kc = 0; kc < 256; kc += 32) {
        for (int idx = tid; idx < 32*64; idx += 256) {
            int o = idx >> 5, k = idx & 31;
            a_s[k*68 + o] = wf[(size_t)(o0 + o)*256 + kc + k];
        }
        for (int idx = tid; idx < 32*64; idx += 256) {
            int k = idx >> 6, n = idx & 63;
            int kk = kc + k;
            b_s[k*64 + n] =
                g_att[(((size_t)(kk >> 6)*NB + b)*64 + (kk & 63))*NPIX + n0 + n];
        }
        __syncthreads();
        #pragma unroll
        for (int k = 0; k < 32; k++) {
            float4 a4 = *(const float4*)&a_s[k*68 + o4];
            float4 b4 = *(const float4*)&b_s[k*64 + n4];
            float av[4] = {a4.x, a4.y, a4.z, a4.w};
            float bv[4] = {b4.x, b4.y, b4.z, b4.w};
            #pragma unroll
            for (int i = 0; i < 4; i++)
                #pragma unroll
                for (int j = 0; j < 4; j++) acc[i][j] += av[i] * bv[j];
        }
        __syncthreads();
    }
    float4 bf4 = *(const float4*)&bf[o0 + o4];
    float bb[4] = {bf4.x, bf4.y, bf4.z, bf4.w};
    #pragma unroll
    for (int i = 0; i < 4; i++) {
        float4 r = make_float4(acc[i][0] + bb[i], acc[i][1] + bb[i],
                               acc[i][2] + bb[i], acc[i][3] + bb[i]);
        *(float4*)&out[((size_t)b*256 + o0 + o4 + i)*NPIX + n0 + n4] = r;
    }
}

// ---------------- launch ----------------------------------------------------
extern "C" void kernel_launch(void* const* d_in, const int* in_sizes, int n_in,
                              void* d_out, int out_size)
{
    const float* x     = (const float*)d_in[0];
    const float* w3    = (const float*)d_in[1];
    const float* b3    = (const float*)d_in[2];
    const float* w5    = (const float*)d_in[3];
    const float* b5    = (const float*)d_in[4];
    const float* w7    = (const float*)d_in[5];
    const float* b7    = (const float*)d_in[6];
    const float* w9    = (const float*)d_in[7];
    const float* b9    = (const float*)d_in[8];
    const float* wqkv  = (const float*)d_in[9];
    const float* wproj = (const float*)d_in[10];
    const float* bproj = (const float*)d_in[11];
    const float* wf    = (const float*)d_in[12];
    const float* bf    = (const float*)d_in[13];
    const float* scale = (const float*)d_in[14];
    float* out = (float*)d_out;

    dim3 gconv(5, 64, 16);
    dwconv_kernel<3><<<gconv, 320>>>(x, w3, b3, 0);
    dwconv_kernel<5><<<gconv, 320>>>(x, w5, b5, 1);
    dwconv_kernel<7><<<gconv, 320>>>(x, w7, b7, 2);
    dwconv_kernel<9><<<gconv, 320>>>(x, w9, b9, 3);

    static bool attr_set = false;
    if (!attr_set) {
        cudaFuncSetAttribute(qkv_kernel,
                             cudaFuncAttributeMaxDynamicSharedMemorySize, 65536);
        attr_set = true;
    }
    qkv_kernel<<<dim3(100, 64), 256, 65536>>>(wqkv);
    qsoftmax_kernel<<<4096, 256>>>();
    ctx_kernel<<<512, 256>>>();
    attn_out_kernel<<<dim3(200, 64), 256>>>(wproj, bproj, scale);
    final_kernel<<<dim3(100, 4, 16), 256>>>(wf, bf, out);
}